// round 1
// baseline (speedup 1.0000x reference)
#include <cuda_runtime.h>
#include <math.h>

// ============================================================================
// EnsembleRatioModel — round 1 baseline
//
// Structure: chain of fused (ReLU-on-load) GEMM+bias kernels + a final
// dot/sigmoid/mask kernel. All fp32, with Blackwell packed fma.rn.f32x2
// (FFMA2) accumulators to double the scalar-fp32 FLOP rate.
//
// Output packing assumption (float32, concatenated flat, reference order):
//   [0,          N*512)  repr_                 [N, 512]
//   [N*512,      +3N)    r_hat * mask          [P, N] (p-major)
//   [N*512+3N,   +3N)    s_hat * mask          [P, N]
//   [N*512+6N,   +3N)    mask (1.0 / 0.0)      [P, N]
// ============================================================================

#define GN 131072
#define BM 128
#define BN 128
#define BK 8
#define TM 8
#define TN 8

// Scratch activations (ping-pong), 256 MB each. Static __device__ arrays per
// the allocation rules.
__device__ float g_bufA[67108864];   // [N, 512]
__device__ float g_bufB[67108864];   // [N, 512] (only [N,256] used for sub layer 1)

// ---- packed f32x2 helpers (Blackwell FFMA2 path) ---------------------------
__device__ __forceinline__ unsigned long long pack2(float a, float b) {
    unsigned long long r;
    asm("mov.b64 %0, {%1, %2};" : "=l"(r) : "f"(a), "f"(b));
    return r;
}
__device__ __forceinline__ float2 unpack2(unsigned long long v) {
    float2 f;
    asm("mov.b64 {%0, %1}, %2;" : "=f"(f.x), "=f"(f.y) : "l"(v));
    return f;
}
__device__ __forceinline__ void fma2(unsigned long long& d,
                                     unsigned long long a,
                                     unsigned long long b) {
    asm("fma.rn.f32x2 %0, %1, %2, %0;" : "+l"(d) : "l"(a), "l"(b));
}

// ---- C[M,N] = relu(A[M,K]) @ W[K,N] + bias[N] -------------------------------
// A row-major [M,K], W row-major [K,N]. M % 128 == 0, N % 128 == 0, K % 8 == 0.
__global__ void __launch_bounds__(256, 2)
gemm_relu_bias(const float* __restrict__ A, const float* __restrict__ W,
               const float* __restrict__ bias, float* __restrict__ C,
               int M, int N, int K)
{
    __shared__ float As[BK][BM];   // A tile, transposed, ReLU applied
    __shared__ float Ws[BK][BN];

    const int tid = threadIdx.x;
    const int tx  = tid & 15;        // 0..15  -> output col group
    const int ty  = tid >> 4;        // 0..15  -> output row group
    const int bm  = blockIdx.y * BM;
    const int bn  = blockIdx.x * BN;

    // global->shared load mapping
    const int arow = tid >> 1;          // 0..127
    const int acol = (tid & 1) << 2;    // 0 or 4
    const int wrow = tid >> 5;          // 0..7
    const int wcol = (tid & 31) << 2;   // 0..124

    const float* Ap = A + (size_t)(bm + arow) * K + acol;
    const float* Wp = W + (size_t)wrow * N + bn + wcol;

    unsigned long long acc[TM][TN / 2];
#pragma unroll
    for (int i = 0; i < TM; i++)
#pragma unroll
        for (int j = 0; j < TN / 2; j++) acc[i][j] = 0ull;

    for (int k0 = 0; k0 < K; k0 += BK) {
        float4 av = *(const float4*)(Ap + k0);
        As[acol + 0][arow] = fmaxf(av.x, 0.f);
        As[acol + 1][arow] = fmaxf(av.y, 0.f);
        As[acol + 2][arow] = fmaxf(av.z, 0.f);
        As[acol + 3][arow] = fmaxf(av.w, 0.f);
        *(float4*)&Ws[wrow][wcol] = *(const float4*)(Wp + (size_t)k0 * N);
        __syncthreads();

#pragma unroll
        for (int k = 0; k < BK; k++) {
            float4 a0 = *(const float4*)&As[k][ty * TM];
            float4 a1 = *(const float4*)&As[k][ty * TM + 4];
            const ulonglong2* wp2 = (const ulonglong2*)&Ws[k][tx * TN];
            ulonglong2 w01 = wp2[0];
            ulonglong2 w23 = wp2[1];
            unsigned long long rb[4] = {w01.x, w01.y, w23.x, w23.y};
            float ra[TM] = {a0.x, a0.y, a0.z, a0.w, a1.x, a1.y, a1.z, a1.w};
#pragma unroll
            for (int i = 0; i < TM; i++) {
                unsigned long long a2 = pack2(ra[i], ra[i]);
#pragma unroll
                for (int j = 0; j < TN / 2; j++) fma2(acc[i][j], a2, rb[j]);
            }
        }
        __syncthreads();
    }

    float bv[TN];
#pragma unroll
    for (int j = 0; j < TN; j++) bv[j] = bias[bn + tx * TN + j];

#pragma unroll
    for (int i = 0; i < TM; i++) {
        float2 p0 = unpack2(acc[i][0]);
        float2 p1 = unpack2(acc[i][1]);
        float2 p2 = unpack2(acc[i][2]);
        float2 p3 = unpack2(acc[i][3]);
        size_t off = (size_t)(bm + ty * TM + i) * N + bn + tx * TN;
        float4 v0 = make_float4(p0.x + bv[0], p0.y + bv[1], p1.x + bv[2], p1.y + bv[3]);
        float4 v1 = make_float4(p2.x + bv[4], p2.y + bv[5], p3.x + bv[6], p3.y + bv[7]);
        *(float4*)(C + off)     = v0;
        *(float4*)(C + off + 4) = v1;
    }
}

// ---- final: logit = relu(s1) . SW2[p] + Sb2[p]; sigmoid/clip/ratio/mask -----
__global__ void subnet_final(const float* __restrict__ s1,      // [N, 256]
                             const float* __restrict__ SW2,     // [3, 256]
                             const float* __restrict__ Sb2,     // [3]
                             const int*   __restrict__ y,       // [N]
                             const int*   __restrict__ pairs,   // [3, 2]
                             int p,
                             float* __restrict__ out_r,
                             float* __restrict__ out_s,
                             float* __restrict__ out_m,
                             int Nrows)
{
    __shared__ float w[256];
    const int tid = threadIdx.x;
    w[tid] = SW2[p * 256 + tid];
    __syncthreads();

    const float sb = Sb2[p];
    const int pa = pairs[2 * p + 0];
    const int pb = pairs[2 * p + 1];

    const int lane = tid & 31;
    const int warp = tid >> 5;
    const int warps_per_blk = blockDim.x >> 5;
    const int gw = blockIdx.x * warps_per_blk + warp;
    const int warps_total = gridDim.x * warps_per_blk;

    for (int n = gw; n < Nrows; n += warps_total) {
        const float* row = s1 + (size_t)n * 256;
        float acc = 0.f;
#pragma unroll
        for (int j = 0; j < 8; j++) {
            int c = lane + 32 * j;
            acc += fmaxf(row[c], 0.f) * w[c];
        }
#pragma unroll
        for (int o = 16; o > 0; o >>= 1)
            acc += __shfl_xor_sync(0xFFFFFFFFu, acc, o);

        if (lane == 0) {
            float logit = acc + sb;
            float s = 1.f / (1.f + expf(-logit));
            s = fmaxf(s, 1e-9f);
            float r = (1.f - s) / s;
            int yv = y[n];
            float m = (yv == pa || yv == pb) ? 1.f : 0.f;
            out_r[n] = r * m;
            out_s[n] = s * m;
            out_m[n] = m;
        }
    }
}

// ============================================================================
extern "C" void kernel_launch(void* const* d_in, const int* in_sizes, int n_in,
                              void* d_out, int out_size)
{
    const float* x     = (const float*)d_in[0];
    const int*   y     = (const int*)  d_in[1];
    const int*   pairs = (const int*)  d_in[2];
    const float* W0    = (const float*)d_in[3];
    const float* b0    = (const float*)d_in[4];
    const float* W1    = (const float*)d_in[5];
    const float* b1    = (const float*)d_in[6];
    const float* W2    = (const float*)d_in[7];
    const float* b2    = (const float*)d_in[8];
    const float* SW0   = (const float*)d_in[9];
    const float* Sb0   = (const float*)d_in[10];
    const float* SW1   = (const float*)d_in[11];
    const float* Sb1   = (const float*)d_in[12];
    const float* SW2   = (const float*)d_in[13];
    const float* Sb2   = (const float*)d_in[14];

    const int M = GN;
    float* out   = (float*)d_out;
    float* repr  = out;                                  // [N, 512]
    float* r_seg = out + (size_t)M * 512;                // [3, N]
    float* s_seg = r_seg + 3 * (size_t)M;                // [3, N]
    float* m_seg = s_seg + 3 * (size_t)M;                // [3, N]

    float *bufA = nullptr, *bufB = nullptr;
    cudaGetSymbolAddress((void**)&bufA, g_bufA);
    cudaGetSymbolAddress((void**)&bufB, g_bufB);

    dim3 blk(256);
    dim3 g512(512 / BN, M / BM);   // (4, 1024)
    dim3 g256(256 / BN, M / BM);   // (2, 1024)

    // trunk
    gemm_relu_bias<<<g512, blk>>>(x,    W0, b0, bufA, M, 512, 64);
    gemm_relu_bias<<<g512, blk>>>(bufA, W1, b1, bufB, M, 512, 512);
    gemm_relu_bias<<<g512, blk>>>(bufB, W2, b2, repr, M, 512, 512);

    // per-pair subnetworks
    for (int p = 0; p < 3; p++) {
        gemm_relu_bias<<<g512, blk>>>(repr, SW0 + (size_t)p * 512 * 512,
                                      Sb0 + p * 512, bufA, M, 512, 512);
        gemm_relu_bias<<<g256, blk>>>(bufA, SW1 + (size_t)p * 512 * 256,
                                      Sb1 + p * 256, bufB, M, 256, 512);
        subnet_final<<<512, 256>>>(bufB, SW2, Sb2, y, pairs, p,
                                   r_seg + (size_t)p * M,
                                   s_seg + (size_t)p * M,
                                   m_seg + (size_t)p * M, M);
    }
}